// round 13
// baseline (speedup 1.0000x reference)
#include <cuda_runtime.h>
#include <cstdint>

// OneDilate: out = 10x10 depthwise box filter of (1-x)*0.5, replicate pad 4.
// x: [32,3,512,512] f32 -> out: [32,3,511,511] f32.
// out = 50 - 0.5 * (sum of 100 raw taps).
//
// R11 structure with single prefetch buffer (16 regs freed) for occupancy:
//  - vertical sliding 10-sum: bottoms prefetched into a 16-reg buffer,
//    tops re-read from gmem (guaranteed L1-hot: loaded ~10 rows earlier),
//    batched x4 so the running-sum chain stalls once per 4 rows.
//  - V double-buffered in smem, ONE __syncthreads per chunk.
//  - consume: 4 outputs/thread via 4x LDS.128, strided STG.32 (R11-proven).
//  - __launch_bounds__(160, 8): 8 CTAs/SM -> 40 warps (62% occ target).

#define IN_H   512
#define IN_W   512
#define OUT_H  511
#define OUT_W  511
#define PLANES 96
#define TILE_X 128
#define TILE_Y 128
#define CH     16
#define NCHUNK 8           // TILE_Y / CH
#define VW     137         // TILE_X + 9 vertical columns
#define VSTR   140         // padded row stride (16B aligned, conflict-free)
#define NT     160         // 5 warps

// One pipeline step: produce V rows for chunk CK (bottoms from buf, tops
// re-read from L1 in batches of 4), prefetch chunk CK+1 into buf (values
// already consumed), single barrier, consume chunk CK from smem VB.
#define STEP(CK, VB) do {                                                    \
    const int jb = ty0 + (CK) * CH;                                          \
    if (vrole) {                                                             \
        _Pragma("unroll")                                                    \
        for (int b4 = 0; b4 < CH; b4 += 4) {                                 \
            int g0 = jb + b4 - 4; g0 = (g0 < 0) ? 0 : g0;                    \
            int g1 = jb + b4 - 3; g1 = (g1 < 0) ? 0 : g1;                    \
            int g2 = jb + b4 - 2; g2 = (g2 < 0) ? 0 : g2;                    \
            int g3 = jb + b4 - 1; g3 = (g3 < 0) ? 0 : g3;                    \
            float t0 = xc[g0 * IN_W];          /* L1-hot top re-reads */     \
            float t1 = xc[g1 * IN_W];                                        \
            float t2 = xc[g2 * IN_W];                                        \
            float t3 = xc[g3 * IN_W];                                        \
            vs += buf[b4+0]; VB[(b4+0)*VSTR + t] = vs; vs -= t0;             \
            vs += buf[b4+1]; VB[(b4+1)*VSTR + t] = vs; vs -= t1;             \
            vs += buf[b4+2]; VB[(b4+2)*VSTR + t] = vs; vs -= t2;             \
            vs += buf[b4+3]; VB[(b4+3)*VSTR + t] = vs; vs -= t3;             \
        }                                                                    \
        if ((CK) < NCHUNK - 1) {                                             \
            _Pragma("unroll")                                                \
            for (int jj = 0; jj < CH; jj++) {                                \
                int g = jb + CH + jj + 5;                                    \
                g = (g > IN_H - 1) ? IN_H - 1 : g;                           \
                buf[jj] = xc[g * IN_W];        /* batch of 16 LDGs, MLP */   \
            }                                                                \
        }                                                                    \
    }                                                                        \
    __syncthreads();                                                         \
    for (int item = t; item < CH * 32; item += NT) {                         \
        const int jj = item >> 5;                                            \
        const int l  = item & 31;                                            \
        const float4* __restrict__ Vv = (const float4*)(VB + jj*VSTR + 4*l); \
        float4 a = Vv[0], b = Vv[1], c4 = Vv[2], d = Vv[3];                  \
        float s0 = ((a.x + a.y) + (a.z + a.w))                               \
                 + ((b.x + b.y) + (b.z + b.w)) + (c4.x + c4.y);              \
        float s1 = s0 - a.x + c4.z;                                          \
        float s2 = s1 - a.y + c4.w;                                          \
        float s3 = s2 - a.z + d.x;                                           \
        const int oy = jb + jj;                                              \
        const int ox = tx0 + 4 * l;                                          \
        if (oy < OUT_H) {                                                    \
            float* __restrict__ o = op + (size_t)oy * OUT_W + ox;            \
            if (ox + 3 < OUT_W) {                                            \
                o[0] = fmaf(s0, -0.5f, 50.0f);                               \
                o[1] = fmaf(s1, -0.5f, 50.0f);                               \
                o[2] = fmaf(s2, -0.5f, 50.0f);                               \
                o[3] = fmaf(s3, -0.5f, 50.0f);                               \
            } else {                                                         \
                if (ox     < OUT_W) o[0] = fmaf(s0, -0.5f, 50.0f);           \
                if (ox + 1 < OUT_W) o[1] = fmaf(s1, -0.5f, 50.0f);           \
                if (ox + 2 < OUT_W) o[2] = fmaf(s2, -0.5f, 50.0f);           \
            }                                                                \
        }                                                                    \
    }                                                                        \
} while (0)

__global__ __launch_bounds__(NT, 8)
void onedilate_kernel(const float* __restrict__ x, float* __restrict__ out)
{
    __shared__ __align__(16) float V[2][CH * VSTR];   // 17,920 B

    const int tx0 = blockIdx.x * TILE_X;
    const int ty0 = blockIdx.y * TILE_Y;
    const int p   = blockIdx.z;
    const float* __restrict__ xp = x   + (size_t)p * IN_H * IN_W;
    float* __restrict__       op = out + (size_t)p * OUT_H * OUT_W;
    const int t = threadIdx.x;

    // vertical role: one input column per thread (clamped = replicate pad)
    int col = tx0 - 4 + t;
    col = (col < 0) ? 0 : (col > IN_W - 1 ? IN_W - 1 : col);
    const float* __restrict__ xc = xp + col;
    const bool vrole = (t < VW);

    float buf[CH];
    float vs = 0.0f;

    if (vrole) {
        // warm-up: vs = sum of x rows ty0-4 .. ty0+4 (clamped)
        #pragma unroll
        for (int k = 0; k < 9; k++) {
            int g = ty0 - 4 + k;
            g = (g < 0) ? 0 : (g > IN_H - 1 ? IN_H - 1 : g);
            vs += xc[g * IN_W];
        }
        // prefetch chunk 0 bottoms: rows ty0+5 .. ty0+20 (clamped)
        #pragma unroll
        for (int jj = 0; jj < CH; jj++) {
            int g = ty0 + 5 + jj;
            g = (g > IN_H - 1) ? IN_H - 1 : g;
            buf[jj] = xc[g * IN_W];
        }
    }

    float* __restrict__ V0 = &V[0][0];
    float* __restrict__ V1 = &V[1][0];

    // single barrier per chunk: consume(ck) sits between barrier(ck) and
    // barrier(ck+1); produce(ck+2) into the same buffer is after barrier(ck+1).
    for (int ck = 0; ck < NCHUNK; ck += 2) {
        STEP(ck,     V0);
        STEP(ck + 1, V1);
    }
}

extern "C" void kernel_launch(void* const* d_in, const int* in_sizes, int n_in,
                              void* d_out, int out_size)
{
    const float* x = (const float*)d_in[0];
    float* out = (float*)d_out;

    dim3 grid((OUT_W + TILE_X - 1) / TILE_X,   // 4
              (OUT_H + TILE_Y - 1) / TILE_Y,   // 4
              PLANES);                          // 96 -> 1536 CTAs (one wave)
    onedilate_kernel<<<grid, NT>>>(x, out);
}